// round 16
// baseline (speedup 1.0000x reference)
#include <cuda_runtime.h>
#include <cuda_bf16.h>
#include <math.h>
#include <stdint.h>

#define D 512
#define HID 256
#define B 512
#define S1 25
#define S2 10
#define NCLS 50
#define M1 (B * S2)    // 5120

// ---------------- scratch: combined hi/lo planes (lo = base + N elems) ----
__device__ __align__(16) __nv_bfloat16 g_ah1[2 * M1 * D];   // gathered h1
__device__ __align__(16) __nv_bfloat16 g_ag2[2 * M1 * D];   // mean(h2)
__device__ __align__(16) __nv_bfloat16 g_ah0[2 * B * D];    // gathered h0
__device__ __align__(16) __nv_bfloat16 g_ag1[2 * B * D];    // mean(h1)
__device__ __align__(16) __nv_bfloat16 g_n0[2 * B * D];     // layer0 hop0 out
__device__ __align__(16) __nv_bfloat16 g_agn1[2 * B * D];   // mean(n1)
__device__ __align__(16) __nv_bfloat16 g_wt[2 * 4 * HID * D]; // 4 W^T mats
__device__ __align__(16) float g_n1[M1 * D];                // layer0 hop1 out fp32
__device__ __align__(16) float g_out[B * D];                // layer1 out fp32

#define WLO (4 * HID * D)      // wt lo-plane elem offset
#define MOFF ((long)M1 * D)
#define BOFF ((long)B * D)
#define WSZ  ((long)HID * D)

// ======================= helpers =======================
__device__ __forceinline__ uint32_t smem_u32(const void* p) {
    uint32_t a;
    asm("{ .reg .u64 t; cvta.to.shared.u64 t, %1; cvt.u32.u64 %0, t; }" : "=r"(a) : "l"(p));
    return a;
}
__device__ __forceinline__ void cvt2(float x, float y, uint32_t& hp, uint32_t& lp) {
    __nv_bfloat16 hx = __float2bfloat16_rn(x);
    __nv_bfloat16 hy = __float2bfloat16_rn(y);
    __nv_bfloat16 lx = __float2bfloat16_rn(x - __bfloat162float(hx));
    __nv_bfloat16 ly = __float2bfloat16_rn(y - __bfloat162float(hy));
    hp = (uint32_t)__bfloat16_as_ushort(hx) | ((uint32_t)__bfloat16_as_ushort(hy) << 16);
    lp = (uint32_t)__bfloat16_as_ushort(lx) | ((uint32_t)__bfloat16_as_ushort(ly) << 16);
}

#define MMA_BF16(d, a0, a1, a2, a3, b0, b1) \
    asm volatile( \
        "mma.sync.aligned.m16n8k16.row.col.f32.bf16.bf16.f32 " \
        "{%0,%1,%2,%3}, {%4,%5,%6,%7}, {%8,%9}, {%0,%1,%2,%3};" \
        : "+f"((d)[0]), "+f"((d)[1]), "+f"((d)[2]), "+f"((d)[3]) \
        : "r"(a0), "r"(a1), "r"(a2), "r"(a3), "r"(b0), "r"(b1))

#define LDSM4(r, addr) \
    asm volatile("ldmatrix.sync.aligned.m8n8.x4.shared.b16 {%0,%1,%2,%3}, [%4];" \
        : "=r"((r)[0]), "=r"((r)[1]), "=r"((r)[2]), "=r"((r)[3]) : "r"(addr))

#define CP_ASYNC16(dst, src) \
    asm volatile("cp.async.ca.shared.global [%0], [%1], 16;" :: "r"(dst), "l"(src))
#define CP_COMMIT() asm volatile("cp.async.commit_group;" ::: "memory")
#define CP_WAIT1()  asm volatile("cp.async.wait_group 1;" ::: "memory")

// swizzled smem offset: rows of 64B (32 bf16), 4x16B chunks, xor (row>>1)&3
__device__ __forceinline__ uint32_t sws(int row, int chunk) {
    return (uint32_t)((row << 6) + ((chunk ^ ((row >> 1) & 3)) << 4));
}

// ======================================================================
// PREP kernel: all independent gathers/means/conversions in ONE launch.
// ======================================================================
__global__ void prep_kernel(const float* __restrict__ feat,
                            const int* __restrict__ samples0,
                            const int* __restrict__ samples1,
                            const int* __restrict__ samples2,
                            const float* __restrict__ W0, const float* __restrict__ W1,
                            const float* __restrict__ W2, const float* __restrict__ W3,
                            __nv_bfloat16* __restrict__ ah1,
                            __nv_bfloat16* __restrict__ ag1,
                            __nv_bfloat16* __restrict__ ah0,
                            __nv_bfloat16* __restrict__ ag2,
                            __nv_bfloat16* __restrict__ wt)
{
    const int blk = blockIdx.x;
    const int c   = threadIdx.x;               // 0..127

    if (blk < M1) {
        // ---- mean of S1=25 gathered rows -> ag2; 5x5 batches for MLP=5
        const int g = blk;
        float4 ch[5];
#pragma unroll
        for (int j = 0; j < 5; ++j) ch[j] = make_float4(0.f, 0.f, 0.f, 0.f);
#pragma unroll
        for (int b5 = 0; b5 < 5; ++b5) {
            float4 v[5];
#pragma unroll
            for (int j = 0; j < 5; ++j) {
                long r = (long)samples2[g * S1 + b5 * 5 + j];
                v[j] = __ldg((const float4*)(feat + r * (long)D) + c);
            }
#pragma unroll
            for (int j = 0; j < 5; ++j) {
                ch[j].x += v[j].x; ch[j].y += v[j].y;
                ch[j].z += v[j].z; ch[j].w += v[j].w;
            }
        }
        float4 a;
        a.x = ((ch[0].x + ch[1].x) + (ch[2].x + ch[3].x)) + ch[4].x;
        a.y = ((ch[0].y + ch[1].y) + (ch[2].y + ch[3].y)) + ch[4].y;
        a.z = ((ch[0].z + ch[1].z) + (ch[2].z + ch[3].z)) + ch[4].z;
        a.w = ((ch[0].w + ch[1].w) + (ch[2].w + ch[3].w)) + ch[4].w;
        const float inv = 1.f / (float)S1;
        uint32_t h01, l01, h23, l23;
        cvt2(a.x * inv, a.y * inv, h01, l01);
        cvt2(a.z * inv, a.w * inv, h23, l23);
        ((uint2*)ag2)[(long)g * 128 + c] = make_uint2(h01, h23);
        ((uint2*)(ag2 + MOFF))[(long)g * 128 + c] = make_uint2(l01, l23);
    } else if (blk < M1 + B) {
        // ---- fused gather(samples1) -> ah1 planes + mean -> ag1 planes
        const int b = blk - M1;
        float4 acc = make_float4(0.f, 0.f, 0.f, 0.f);
        float4 v[S2];
#pragma unroll
        for (int s = 0; s < S2; ++s) {
            long r = (long)samples1[b * S2 + s];
            v[s] = __ldg((const float4*)(feat + r * (long)D) + c);
        }
#pragma unroll
        for (int s = 0; s < S2; ++s) {
            long row = b * S2 + s;
            uint32_t h01, l01, h23, l23;
            cvt2(v[s].x, v[s].y, h01, l01); cvt2(v[s].z, v[s].w, h23, l23);
            ((uint2*)ah1)[row * 128 + c] = make_uint2(h01, h23);
            ((uint2*)(ah1 + MOFF))[row * 128 + c] = make_uint2(l01, l23);
            acc.x += v[s].x; acc.y += v[s].y; acc.z += v[s].z; acc.w += v[s].w;
        }
        const float inv = 1.f / (float)S2;
        uint32_t h01, l01, h23, l23;
        cvt2(acc.x * inv, acc.y * inv, h01, l01);
        cvt2(acc.z * inv, acc.w * inv, h23, l23);
        ((uint2*)ag1)[(long)b * 128 + c] = make_uint2(h01, h23);
        ((uint2*)(ag1 + BOFF))[(long)b * 128 + c] = make_uint2(l01, l23);
    } else if (blk < M1 + 2 * B) {
        // ---- gather(samples0) -> ah0 planes
        const int g = blk - M1 - B;
        long r = (long)samples0[g];
        float4 v = __ldg((const float4*)(feat + r * (long)D) + c);
        uint32_t h01, l01, h23, l23;
        cvt2(v.x, v.y, h01, l01); cvt2(v.z, v.w, h23, l23);
        ((uint2*)ah0)[(long)g * 128 + c] = make_uint2(h01, h23);
        ((uint2*)(ah0 + BOFF))[(long)g * 128 + c] = make_uint2(l01, l23);
    } else {
        // ---- weight convert+transpose: 4 x [512,256] -> [256,512] hi/lo
        const int idx = (blk - M1 - 2 * B) * 128 + c;   // 0..524287
        const int n = idx & (HID - 1);
        const int k = (idx >> 8) & (D - 1);
        const int m = idx >> 17;
        const float* W = (m == 0) ? W0 : (m == 1) ? W1 : (m == 2) ? W2 : W3;
        float v = __ldg(W + (long)k * HID + n);
        __nv_bfloat16 hb = __float2bfloat16_rn(v);
        __nv_bfloat16 lb = __float2bfloat16_rn(v - __bfloat162float(hb));
        __nv_bfloat16* h = wt + (long)m * WSZ;
        h[(long)n * D + k] = hb;
        h[WLO + (long)n * D + k] = lb;
    }
}

// ---------------- mean of S2 dense fp32 rows -> hi/lo planes; zero outb ---
__global__ void mean_n1_kernel(const float* __restrict__ src,
                               __nv_bfloat16* __restrict__ o,
                               float* __restrict__ outb)
{
    const int g = blockIdx.x, c = threadIdx.x;
    ((float4*)(outb + (long)g * D))[c] = make_float4(0.f, 0.f, 0.f, 0.f);

    float4 a0 = make_float4(0.f, 0.f, 0.f, 0.f);
    float4 a1 = make_float4(0.f, 0.f, 0.f, 0.f);
#pragma unroll
    for (int s = 0; s < S2; ++s) {
        float4 v = __ldg((const float4*)(src + (long)(g * S2 + s) * D) + c);
        if (s & 1) { a1.x += v.x; a1.y += v.y; a1.z += v.z; a1.w += v.w; }
        else       { a0.x += v.x; a0.y += v.y; a0.z += v.z; a0.w += v.w; }
    }
    const float inv = 1.f / (float)S2;
    uint32_t h01, l01, h23, l23;
    cvt2((a0.x + a1.x) * inv, (a0.y + a1.y) * inv, h01, l01);
    cvt2((a0.z + a1.z) * inv, (a0.w + a1.w) * inv, h23, l23);
    ((uint2*)o)[(long)g * 128 + c] = make_uint2(h01, h23);
    ((uint2*)(o + BOFF))[(long)g * 128 + c] = make_uint2(l01, l23);
}

// ======================================================================
// GEMM body (R11/R13 inner loop — measured best), k-range for split-K,
// ATOM=1 -> fp32 atomicAdd epilogue.
// ======================================================================
template<int BM, int RELU, int PLANES, int ATOM>
__device__ __forceinline__ void gemm_body(
    const __nv_bfloat16* __restrict__ A, long aoff,
    const __nv_bfloat16* __restrict__ Bw,
    int bm, int bn, int colOff,
    float* __restrict__ C, __nv_bfloat16* __restrict__ Cp, long cpoff,
    char* sm, int ktBeg, int ktEnd)
{
    constexpr int NSPAN = (BM == 128) ? 32 : 16;
    constexpr int NT = NSPAN / 8;
    constexpr int NP = NSPAN / 16;
    constexpr int OFF_AL = BM * 64;
    constexpr int OFF_BH = 2 * BM * 64;
    constexpr int OFF_BL = OFF_BH + 4096;
    constexpr int STG = OFF_BH + 8192;

    const uint32_t sbase = smem_u32(sm);
    const int tid  = threadIdx.x;
    const int warp = tid >> 5, lane = tid & 31;
    const int wm = (BM == 128) ? (warp >> 1) : (warp >> 2);
    const int wn = (BM == 128) ? (warp & 1)  : (warp & 3);

    const int lrow = tid >> 2, lc = tid & 3;
    const char* srcA = (const char*)(A + (long)(bm + lrow) * D) + lc * 16;
    const char* srcB = (const char*)(Bw + (long)(bn + lrow) * D) + lc * 16;
    const long ALO = aoff * 2;
    const long BLO = (long)WLO * 2;
    constexpr long ROW1 = 64 * D * 2;
    const uint32_t d0 = sws(lrow, lc), d1 = sws(lrow + 64, lc);

    float acc[2][NT][4];
#pragma unroll
    for (int mt = 0; mt < 2; ++mt)
#pragma unroll
        for (int nt = 0; nt < NT; ++nt)
#pragma unroll
            for (int q = 0; q < 4; ++q) acc[mt][nt][q] = 0.f;

#pragma unroll
    for (int s = 0; s < 2; ++s) {
        const int kt = ktBeg + s;
        const uint32_t sb = sbase + (kt % 3) * STG;
        const long go = (long)kt * 64;
        CP_ASYNC16(sb + d0,          srcA + go);
        CP_ASYNC16(sb + OFF_AL + d0, srcA + ALO + go);
        if (BM == 128) {
            CP_ASYNC16(sb + d1,          srcA + ROW1 + go);
            CP_ASYNC16(sb + OFF_AL + d1, srcA + ALO + ROW1 + go);
        }
        CP_ASYNC16(sb + OFF_BH + d0, srcB + go);
        CP_ASYNC16(sb + OFF_BL + d0, srcB + BLO + go);
        CP_COMMIT();
    }

#pragma unroll 1
    for (int kt = ktBeg; kt < ktEnd; ++kt) {
        CP_WAIT1();
        __syncthreads();
        if (kt + 2 < ktEnd) {
            const uint32_t nb = sbase + ((kt + 2) % 3) * STG;
            const long go = (long)(kt + 2) * 64;
            CP_ASYNC16(nb + d0,          srcA + go);
            CP_ASYNC16(nb + OFF_AL + d0, srcA + ALO + go);
            if (BM == 128) {
                CP_ASYNC16(nb + d1,          srcA + ROW1 + go);
                CP_ASYNC16(nb + OFF_AL + d1, srcA + ALO + ROW1 + go);
            }
            CP_ASYNC16(nb + OFF_BH + d0, srcB + go);
            CP_ASYNC16(nb + OFF_BL + d0, srcB + BLO + go);
            CP_COMMIT();
        }
        const uint32_t sb = sbase + (kt % 3) * STG;
#pragma unroll
        for (int kk = 0; kk < 2; ++kk) {
            const int kc = kk * 2 + (lane >> 4);
            uint32_t ah[2][4], al[2][4];
            const int arow = wm * 32 + (lane & 15);
#pragma unroll
            for (int mt = 0; mt < 2; ++mt) {
                const uint32_t ad = sb + sws(arow + mt * 16, kc);
                LDSM4(ah[mt], ad);
                LDSM4(al[mt], ad + OFF_AL);
            }
            const int brow = wn * NSPAN + (lane & 7) + ((lane >> 3) & 1) * 8;
#pragma unroll
            for (int np = 0; np < NP; ++np) {
                const uint32_t bd = sb + OFF_BH + sws(brow + np * 16, kc);
                uint32_t rh[4], rl[4];
                LDSM4(rh, bd);
                LDSM4(rl, bd + 4096);
#pragma unroll
                for (int half = 0; half < 2; ++half) {
                    const int nt = 2 * np + half;
#pragma unroll
                    for (int mt = 0; mt < 2; ++mt)
                        MMA_BF16(acc[mt][nt], ah[mt][0], ah[mt][1], ah[mt][2], ah[mt][3],
                                 rh[half], rh[half + 2]);
#pragma unroll
                    for (int mt = 0; mt < 2; ++mt)
                        MMA_BF16(acc[mt][nt], ah[mt][0], ah[mt][1], ah[mt][2], ah[mt][3],
                                 rl[half], rl[half + 2]);
#pragma unroll
                    for (int mt = 0; mt < 2; ++mt)
                        MMA_BF16(acc[mt][nt], al[mt][0], al[mt][1], al[mt][2], al[mt][3],
                                 rh[half], rh[half + 2]);
                }
            }
        }
    }

    const int g = lane >> 2, tg = lane & 3;
#pragma unroll
    for (int mt = 0; mt < 2; ++mt) {
        const int r0 = bm + wm * 32 + mt * 16 + g;
#pragma unroll
        for (int nt = 0; nt < NT; ++nt) {
            const int col = colOff + wn * NSPAN + nt * 8 + tg * 2;
            float v0 = acc[mt][nt][0], v1 = acc[mt][nt][1];
            float v2 = acc[mt][nt][2], v3 = acc[mt][nt][3];
            if (RELU) {
                v0 = fmaxf(v0, 0.f); v1 = fmaxf(v1, 0.f);
                v2 = fmaxf(v2, 0.f); v3 = fmaxf(v3, 0.f);
            }
            if (PLANES) {
                uint32_t h01, l01, h23, l23;
                cvt2(v0, v1, h01, l01);
                cvt2(v2, v3, h23, l23);
                *(uint32_t*)(Cp + (long)r0 * D + col)               = h01;
                *(uint32_t*)(Cp + cpoff + (long)r0 * D + col)       = l01;
                *(uint32_t*)(Cp + (long)(r0 + 8) * D + col)         = h23;
                *(uint32_t*)(Cp + cpoff + (long)(r0 + 8) * D + col) = l23;
            } else if (ATOM) {
                atomicAdd(C + (long)r0 * D + col,           v0);
                atomicAdd(C + (long)r0 * D + col + 1,       v1);
                atomicAdd(C + (long)(r0 + 8) * D + col,     v2);
                atomicAdd(C + (long)(r0 + 8) * D + col + 1, v3);
            } else {
                *(float2*)(C + (long)r0 * D + col)       = make_float2(v0, v1);
                *(float2*)(C + (long)(r0 + 8) * D + col) = make_float2(v2, v3);
            }
        }
    }
}

// ======================================================================
// Layer-0 GEMM kernel: big n1 GEMM (y<40, BM=128) + n0 GEMM (y>=40, BM=64)
// __launch_bounds__(256, 3): regs<=85 so 3 CTAs/SM co-reside (smem 3x72KB=216KB)
// ======================================================================
__global__ void __launch_bounds__(256, 3)
layer0_gemm_kernel(const __nv_bfloat16* __restrict__ ah1,
                   const __nv_bfloat16* __restrict__ ag2,
                   const __nv_bfloat16* __restrict__ ah0,
                   const __nv_bfloat16* __restrict__ ag1,
                   const __nv_bfloat16* __restrict__ wt,
                   float* __restrict__ n1,
                   __nv_bfloat16* __restrict__ n0)
{
    extern __shared__ __align__(16) char sm[];
    const int z = blockIdx.z;
    const int bn = blockIdx.x * 64;
    const int colOff = z * HID + bn;
    const __nv_bfloat16* Bw = wt + (z ? WSZ : 0);

    if (blockIdx.y < M1 / 128) {
        const __nv_bfloat16* A = z ? ag2 : ah1;
        gemm_body<128, 1, 0, 0>(A, MOFF, Bw, blockIdx.y * 128, bn, colOff,
                                n1, nullptr, 0, sm, 0, D / 32);
    } else {
        const __nv_bfloat16* A = z ? ag1 : ah0;
        gemm_body<64, 1, 1, 0>(A, BOFF, Bw, (blockIdx.y - M1 / 128) * 64, bn, colOff,
                               nullptr, n0, BOFF, sm, 0, D / 32);
    }
}

// ---------------- layer-1 GEMM: split-K=2, fp32 atomicAdd epilogue --------
__global__ void __launch_bounds__(256, 3)
layer1_gemm_kernel(const __nv_bfloat16* __restrict__ n0,
                   const __nv_bfloat16* __restrict__ agn1,
                   const __nv_bfloat16* __restrict__ wt,
                   float* __restrict__ outb)
{
    extern __shared__ __align__(16) char sm[];
    const int z = blockIdx.z;
    const int bn = blockIdx.x * 64;
    const int ks = blockIdx.y >> 3;            // k-split half (0/1)
    const int by = blockIdx.y & 7;             // m tile
    const __nv_bfloat16* A  = z ? agn1 : n0;
    const __nv_bfloat16* Bw = wt + (z ? 3 : 2) * WSZ;
    gemm_body<64, 0, 0, 1>(A, BOFF, Bw, by * 64, bn, z * HID + bn,
                           outb, nullptr, 0, sm, ks * 8, ks * 8 + 8);
}

// ---------------- normalize rows of out[512,512], then logits ------------
__global__ void finalize_kernel(const float* __restrict__ outb,
                                const float* __restrict__ Wp,
                                const float* __restrict__ bp,
                                float* __restrict__ logits)
{
    int b = blockIdx.x;
    int t = threadIdx.x;
    __shared__ float row[D];
    __shared__ float wss[4];

    float ss = 0.f;
#pragma unroll
    for (int i = 0; i < 4; ++i) {
        int k = t + i * 128;
        float v = outb[(long)b * D + k];
        row[k] = v;
        ss += v * v;
    }
#pragma unroll
    for (int o = 16; o; o >>= 1) ss += __shfl_xor_sync(0xffffffffu, ss, o);
    if ((t & 31) == 0) wss[t >> 5] = ss;
    __syncthreads();
    float inv = 1.f / fmaxf(sqrtf(wss[0] + wss[1] + wss[2] + wss[3]), 1e-12f);

    if (t < NCLS) {
        float acc = 0.f;
#pragma unroll 8
        for (int k = 0; k < D; ++k) acc = fmaf(row[k], Wp[k * NCLS + t], acc);
        logits[(long)b * NCLS + t] = acc * inv + bp[t];
    }
}

// --------------------------------------------------------------------------
extern "C" void kernel_launch(void* const* d_in, const int* in_sizes, int n_in,
                              void* d_out, int out_size)
{
    const float* features = (const float*)d_in[0];
    const float* W_self0  = (const float*)d_in[1];
    const float* W_neigh0 = (const float*)d_in[2];
    const float* W_self1  = (const float*)d_in[3];
    const float* W_neigh1 = (const float*)d_in[4];
    const float* W_pred   = (const float*)d_in[5];
    const float* b_pred   = (const float*)d_in[6];
    const int*   samples0 = (const int*)d_in[7];
    const int*   samples1 = (const int*)d_in[8];
    const int*   samples2 = (const int*)d_in[9];
    float* logits = (float*)d_out;

    __nv_bfloat16 *ah1, *ag2, *ah0, *ag1, *n0, *agn1, *wt;
    float *n1, *outb;
    cudaGetSymbolAddress((void**)&ah1,  g_ah1);
    cudaGetSymbolAddress((void**)&ag2,  g_ag2);
    cudaGetSymbolAddress((void**)&ah0,  g_ah0);
    cudaGetSymbolAddress((void**)&ag1,  g_ag1);
    cudaGetSymbolAddress((void**)&n0,   g_n0);
    cudaGetSymbolAddress((void**)&agn1, g_agn1);
    cudaGetSymbolAddress((void**)&wt,   g_wt);
    cudaGetSymbolAddress((void**)&n1,   g_n1);
    cudaGetSymbolAddress((void**)&outb, g_out);

    constexpr int SM128 = 3 * (2 * 128 * 64 + 8192);  // 73728
    constexpr int SM64  = 3 * (2 * 64 * 64 + 8192);   // 49152
    cudaFuncSetAttribute(layer0_gemm_kernel, cudaFuncAttributeMaxDynamicSharedMemorySize, SM128);
    cudaFuncSetAttribute(layer1_gemm_kernel, cudaFuncAttributeMaxDynamicSharedMemorySize, SM64);

    // 1) all gathers / means / weight conversion in one launch
    prep_kernel<<<M1 + 2 * B + 4096, 128>>>(
        features, samples0, samples1, samples2,
        W_self0, W_neigh0, W_self1, W_neigh1,
        ah1, ag1, ah0, ag2, wt);

    // 2) layer 0: big n1 GEMM (320 CTAs) + n0 GEMM (64 CTAs) in one launch
    layer0_gemm_kernel<<<dim3(4, M1 / 128 + B / 64, 2), 256, SM128>>>(
        ah1, ag2, ah0, ag1, wt, n1, n0);

    // 3) mean of n1 groups -> planes; also zeroes outb for split-K atomics
    mean_n1_kernel<<<B, 128>>>(n1, agn1, outb);

    // 4) layer 1 GEMM, split-K=2 (128 CTAs)
    layer1_gemm_kernel<<<dim3(4, 16, 2), 256, SM64>>>(n0, agn1, wt, outb);

    // 5) row-normalize + logits
    finalize_kernel<<<B, 128>>>(outb, W_pred, b_pred, logits);
}

// round 17
// speedup vs baseline: 1.0513x; 1.0513x over previous
#include <cuda_runtime.h>
#include <cuda_bf16.h>
#include <math.h>
#include <stdint.h>

#define D 512
#define HID 256
#define B 512
#define S1 25
#define S2 10
#define NCLS 50
#define M1 (B * S2)    // 5120

// ---------------- scratch: combined hi/lo planes (lo = base + N elems) ----
__device__ __align__(16) __nv_bfloat16 g_ah1[2 * M1 * D];   // gathered h1
__device__ __align__(16) __nv_bfloat16 g_ag2[2 * M1 * D];   // mean(h2)
__device__ __align__(16) __nv_bfloat16 g_ah0[2 * B * D];    // gathered h0
__device__ __align__(16) __nv_bfloat16 g_ag1[2 * B * D];    // mean(h1)
__device__ __align__(16) __nv_bfloat16 g_n0[2 * B * D];     // layer0 hop0 out
__device__ __align__(16) __nv_bfloat16 g_agn1[2 * B * D];   // mean(n1)
__device__ __align__(16) __nv_bfloat16 g_wt[2 * 4 * HID * D]; // 4 W^T mats
__device__ __align__(16) float g_n1[M1 * D];                // layer0 hop1 out fp32
__device__ __align__(16) float g_out[B * D];                // layer1 out fp32

#define WLO (4 * HID * D)      // wt lo-plane elem offset
#define MOFF ((long)M1 * D)
#define BOFF ((long)B * D)
#define WSZ  ((long)HID * D)

// ======================= helpers =======================
__device__ __forceinline__ uint32_t smem_u32(const void* p) {
    uint32_t a;
    asm("{ .reg .u64 t; cvta.to.shared.u64 t, %1; cvt.u32.u64 %0, t; }" : "=r"(a) : "l"(p));
    return a;
}
__device__ __forceinline__ void cvt2(float x, float y, uint32_t& hp, uint32_t& lp) {
    __nv_bfloat16 hx = __float2bfloat16_rn(x);
    __nv_bfloat16 hy = __float2bfloat16_rn(y);
    __nv_bfloat16 lx = __float2bfloat16_rn(x - __bfloat162float(hx));
    __nv_bfloat16 ly = __float2bfloat16_rn(y - __bfloat162float(hy));
    hp = (uint32_t)__bfloat16_as_ushort(hx) | ((uint32_t)__bfloat16_as_ushort(hy) << 16);
    lp = (uint32_t)__bfloat16_as_ushort(lx) | ((uint32_t)__bfloat16_as_ushort(ly) << 16);
}

#define MMA_BF16(d, a0, a1, a2, a3, b0, b1) \
    asm volatile( \
        "mma.sync.aligned.m16n8k16.row.col.f32.bf16.bf16.f32 " \
        "{%0,%1,%2,%3}, {%4,%5,%6,%7}, {%8,%9}, {%0,%1,%2,%3};" \
        : "+f"((d)[0]), "+f"((d)[1]), "+f"((d)[2]), "+f"((d)[3]) \
        : "r"(a0), "r"(a1), "r"(a2), "r"(a3), "r"(b0), "r"(b1))

#define LDSM4(r, addr) \
    asm volatile("ldmatrix.sync.aligned.m8n8.x4.shared.b16 {%0,%1,%2,%3}, [%4];" \
        : "=r"((r)[0]), "=r"((r)[1]), "=r"((r)[2]), "=r"((r)[3]) : "r"(addr))

#define CP_ASYNC16(dst, src) \
    asm volatile("cp.async.ca.shared.global [%0], [%1], 16;" :: "r"(dst), "l"(src))
#define CP_COMMIT() asm volatile("cp.async.commit_group;" ::: "memory")
#define CP_WAIT1()  asm volatile("cp.async.wait_group 1;" ::: "memory")

// swizzled smem offset: rows of 64B (32 bf16), 4x16B chunks, xor (row>>1)&3
__device__ __forceinline__ uint32_t sws(int row, int chunk) {
    return (uint32_t)((row << 6) + ((chunk ^ ((row >> 1) & 3)) << 4));
}

// ======================================================================
// PREP kernel: all independent gathers/means/conversions in ONE launch.
// ======================================================================
__global__ void prep_kernel(const float* __restrict__ feat,
                            const int* __restrict__ samples0,
                            const int* __restrict__ samples1,
                            const int* __restrict__ samples2,
                            const float* __restrict__ W0, const float* __restrict__ W1,
                            const float* __restrict__ W2, const float* __restrict__ W3,
                            __nv_bfloat16* __restrict__ ah1,
                            __nv_bfloat16* __restrict__ ag1,
                            __nv_bfloat16* __restrict__ ah0,
                            __nv_bfloat16* __restrict__ ag2,
                            __nv_bfloat16* __restrict__ wt)
{
    const int blk = blockIdx.x;
    const int c   = threadIdx.x;               // 0..127

    if (blk < M1) {
        // ---- mean of S1=25 gathered rows -> ag2; 5x5 batches for MLP=5
        const int g = blk;
        float4 ch[5];
#pragma unroll
        for (int j = 0; j < 5; ++j) ch[j] = make_float4(0.f, 0.f, 0.f, 0.f);
#pragma unroll
        for (int b5 = 0; b5 < 5; ++b5) {
            float4 v[5];
#pragma unroll
            for (int j = 0; j < 5; ++j) {
                long r = (long)samples2[g * S1 + b5 * 5 + j];
                v[j] = __ldg((const float4*)(feat + r * (long)D) + c);
            }
#pragma unroll
            for (int j = 0; j < 5; ++j) {
                ch[j].x += v[j].x; ch[j].y += v[j].y;
                ch[j].z += v[j].z; ch[j].w += v[j].w;
            }
        }
        float4 a;
        a.x = ((ch[0].x + ch[1].x) + (ch[2].x + ch[3].x)) + ch[4].x;
        a.y = ((ch[0].y + ch[1].y) + (ch[2].y + ch[3].y)) + ch[4].y;
        a.z = ((ch[0].z + ch[1].z) + (ch[2].z + ch[3].z)) + ch[4].z;
        a.w = ((ch[0].w + ch[1].w) + (ch[2].w + ch[3].w)) + ch[4].w;
        const float inv = 1.f / (float)S1;
        uint32_t h01, l01, h23, l23;
        cvt2(a.x * inv, a.y * inv, h01, l01);
        cvt2(a.z * inv, a.w * inv, h23, l23);
        ((uint2*)ag2)[(long)g * 128 + c] = make_uint2(h01, h23);
        ((uint2*)(ag2 + MOFF))[(long)g * 128 + c] = make_uint2(l01, l23);
    } else if (blk < M1 + B) {
        // ---- fused gather(samples1) -> ah1 planes + mean -> ag1 planes
        const int b = blk - M1;
        float4 acc = make_float4(0.f, 0.f, 0.f, 0.f);
        float4 v[S2];
#pragma unroll
        for (int s = 0; s < S2; ++s) {
            long r = (long)samples1[b * S2 + s];
            v[s] = __ldg((const float4*)(feat + r * (long)D) + c);
        }
#pragma unroll
        for (int s = 0; s < S2; ++s) {
            long row = b * S2 + s;
            uint32_t h01, l01, h23, l23;
            cvt2(v[s].x, v[s].y, h01, l01); cvt2(v[s].z, v[s].w, h23, l23);
            ((uint2*)ah1)[row * 128 + c] = make_uint2(h01, h23);
            ((uint2*)(ah1 + MOFF))[row * 128 + c] = make_uint2(l01, l23);
            acc.x += v[s].x; acc.y += v[s].y; acc.z += v[s].z; acc.w += v[s].w;
        }
        const float inv = 1.f / (float)S2;
        uint32_t h01, l01, h23, l23;
        cvt2(acc.x * inv, acc.y * inv, h01, l01);
        cvt2(acc.z * inv, acc.w * inv, h23, l23);
        ((uint2*)ag1)[(long)b * 128 + c] = make_uint2(h01, h23);
        ((uint2*)(ag1 + BOFF))[(long)b * 128 + c] = make_uint2(l01, l23);
    } else if (blk < M1 + 2 * B) {
        // ---- gather(samples0) -> ah0 planes
        const int g = blk - M1 - B;
        long r = (long)samples0[g];
        float4 v = __ldg((const float4*)(feat + r * (long)D) + c);
        uint32_t h01, l01, h23, l23;
        cvt2(v.x, v.y, h01, l01); cvt2(v.z, v.w, h23, l23);
        ((uint2*)ah0)[(long)g * 128 + c] = make_uint2(h01, h23);
        ((uint2*)(ah0 + BOFF))[(long)g * 128 + c] = make_uint2(l01, l23);
    } else {
        // ---- weight convert+transpose: 4 x [512,256] -> [256,512] hi/lo
        const int idx = (blk - M1 - 2 * B) * 128 + c;   // 0..524287
        const int n = idx & (HID - 1);
        const int k = (idx >> 8) & (D - 1);
        const int m = idx >> 17;
        const float* W = (m == 0) ? W0 : (m == 1) ? W1 : (m == 2) ? W2 : W3;
        float v = __ldg(W + (long)k * HID + n);
        __nv_bfloat16 hb = __float2bfloat16_rn(v);
        __nv_bfloat16 lb = __float2bfloat16_rn(v - __bfloat162float(hb));
        __nv_bfloat16* h = wt + (long)m * WSZ;
        h[(long)n * D + k] = hb;
        h[WLO + (long)n * D + k] = lb;
    }
}

// ---- mean of S2 dense fp32 rows -> hi/lo planes; zero outb (256 thr) ----
__global__ void mean_n1_kernel(const float* __restrict__ src,
                               __nv_bfloat16* __restrict__ o,
                               float* __restrict__ outb)
{
    const int g = blockIdx.x, c2 = threadIdx.x;       // float2 col 0..255
    ((float2*)(outb + (long)g * D))[c2] = make_float2(0.f, 0.f);

    float2 a0 = make_float2(0.f, 0.f);
    float2 a1 = make_float2(0.f, 0.f);
#pragma unroll
    for (int s = 0; s < S2; ++s) {
        float2 v = __ldg((const float2*)(src + (long)(g * S2 + s) * D) + c2);
        if (s & 1) { a1.x += v.x; a1.y += v.y; }
        else       { a0.x += v.x; a0.y += v.y; }
    }
    const float inv = 1.f / (float)S2;
    uint32_t h, l;
    cvt2((a0.x + a1.x) * inv, (a0.y + a1.y) * inv, h, l);
    ((uint32_t*)o)[(long)g * 256 + c2] = h;
    ((uint32_t*)(o + BOFF))[(long)g * 256 + c2] = l;
}

// ======================================================================
// GEMM body — R13 inner loop, but 2-stage cp.async ring (half the smem,
// so 3 CTAs/SM fit). Issue of kt+2 happens after compute(kt) frees its
// slot; it overlaps with compute(kt+1).
// ======================================================================
template<int BM, int RELU, int PLANES, int ATOM>
__device__ __forceinline__ void gemm_body(
    const __nv_bfloat16* __restrict__ A, long aoff,
    const __nv_bfloat16* __restrict__ Bw,
    int bm, int bn, int colOff,
    float* __restrict__ C, __nv_bfloat16* __restrict__ Cp, long cpoff,
    char* sm, int ktBeg, int ktEnd)
{
    constexpr int NSPAN = (BM == 128) ? 32 : 16;
    constexpr int NT = NSPAN / 8;
    constexpr int NP = NSPAN / 16;
    constexpr int OFF_AL = BM * 64;
    constexpr int OFF_BH = 2 * BM * 64;
    constexpr int OFF_BL = OFF_BH + 4096;
    constexpr int STG = OFF_BH + 8192;

    const uint32_t sbase = smem_u32(sm);
    const int tid  = threadIdx.x;
    const int warp = tid >> 5, lane = tid & 31;
    const int wm = (BM == 128) ? (warp >> 1) : (warp >> 2);
    const int wn = (BM == 128) ? (warp & 1)  : (warp & 3);

    const int lrow = tid >> 2, lc = tid & 3;
    const char* srcA = (const char*)(A + (long)(bm + lrow) * D) + lc * 16;
    const char* srcB = (const char*)(Bw + (long)(bn + lrow) * D) + lc * 16;
    const long ALO = aoff * 2;
    const long BLO = (long)WLO * 2;
    constexpr long ROW1 = 64 * D * 2;
    const uint32_t d0 = sws(lrow, lc), d1 = sws(lrow + 64, lc);

    float acc[2][NT][4];
#pragma unroll
    for (int mt = 0; mt < 2; ++mt)
#pragma unroll
        for (int nt = 0; nt < NT; ++nt)
#pragma unroll
            for (int q = 0; q < 4; ++q) acc[mt][nt][q] = 0.f;

#pragma unroll
    for (int s = 0; s < 2; ++s) {
        const int kt = ktBeg + s;
        const uint32_t sb = sbase + (kt & 1) * STG;
        const long go = (long)kt * 64;
        CP_ASYNC16(sb + d0,          srcA + go);
        CP_ASYNC16(sb + OFF_AL + d0, srcA + ALO + go);
        if (BM == 128) {
            CP_ASYNC16(sb + d1,          srcA + ROW1 + go);
            CP_ASYNC16(sb + OFF_AL + d1, srcA + ALO + ROW1 + go);
        }
        CP_ASYNC16(sb + OFF_BH + d0, srcB + go);
        CP_ASYNC16(sb + OFF_BL + d0, srcB + BLO + go);
        CP_COMMIT();
    }

#pragma unroll 1
    for (int kt = ktBeg; kt < ktEnd; ++kt) {
        CP_WAIT1();
        __syncthreads();
        const uint32_t sb = sbase + (kt & 1) * STG;
#pragma unroll
        for (int kk = 0; kk < 2; ++kk) {
            const int kc = kk * 2 + (lane >> 4);
            uint32_t ah[2][4], al[2][4];
            const int arow = wm * 32 + (lane & 15);
#pragma unroll
            for (int mt = 0; mt < 2; ++mt) {
                const uint32_t ad = sb + sws(arow + mt * 16, kc);
                LDSM4(ah[mt], ad);
                LDSM4(al[mt], ad + OFF_AL);
            }
            const int brow = wn * NSPAN + (lane & 7) + ((lane >> 3) & 1) * 8;
#pragma unroll
            for (int np = 0; np < NP; ++np) {
                const uint32_t bd = sb + OFF_BH + sws(brow + np * 16, kc);
                uint32_t rh[4], rl[4];
                LDSM4(rh, bd);
                LDSM4(rl, bd + 4096);
#pragma unroll
                for (int half = 0; half < 2; ++half) {
                    const int nt = 2 * np + half;
#pragma unroll
                    for (int mt = 0; mt < 2; ++mt)
                        MMA_BF16(acc[mt][nt], ah[mt][0], ah[mt][1], ah[mt][2], ah[mt][3],
                                 rh[half], rh[half + 2]);
#pragma unroll
                    for (int mt = 0; mt < 2; ++mt)
                        MMA_BF16(acc[mt][nt], ah[mt][0], ah[mt][1], ah[mt][2], ah[mt][3],
                                 rl[half], rl[half + 2]);
#pragma unroll
                    for (int mt = 0; mt < 2; ++mt)
                        MMA_BF16(acc[mt][nt], al[mt][0], al[mt][1], al[mt][2], al[mt][3],
                                 rh[half], rh[half + 2]);
                }
            }
        }
        __syncthreads();                       // slot kt now free
        if (kt + 2 < ktEnd) {
            const uint32_t nb = sbase + ((kt + 2) & 1) * STG;
            const long go = (long)(kt + 2) * 64;
            CP_ASYNC16(nb + d0,          srcA + go);
            CP_ASYNC16(nb + OFF_AL + d0, srcA + ALO + go);
            if (BM == 128) {
                CP_ASYNC16(nb + d1,          srcA + ROW1 + go);
                CP_ASYNC16(nb + OFF_AL + d1, srcA + ALO + ROW1 + go);
            }
            CP_ASYNC16(nb + OFF_BH + d0, srcB + go);
            CP_ASYNC16(nb + OFF_BL + d0, srcB + BLO + go);
            CP_COMMIT();
        }
    }

    const int g = lane >> 2, tg = lane & 3;
#pragma unroll
    for (int mt = 0; mt < 2; ++mt) {
        const int r0 = bm + wm * 32 + mt * 16 + g;
#pragma unroll
        for (int nt = 0; nt < NT; ++nt) {
            const int col = colOff + wn * NSPAN + nt * 8 + tg * 2;
            float v0 = acc[mt][nt][0], v1 = acc[mt][nt][1];
            float v2 = acc[mt][nt][2], v3 = acc[mt][nt][3];
            if (RELU) {
                v0 = fmaxf(v0, 0.f); v1 = fmaxf(v1, 0.f);
                v2 = fmaxf(v2, 0.f); v3 = fmaxf(v3, 0.f);
            }
            if (PLANES) {
                uint32_t h01, l01, h23, l23;
                cvt2(v0, v1, h01, l01);
                cvt2(v2, v3, h23, l23);
                *(uint32_t*)(Cp + (long)r0 * D + col)               = h01;
                *(uint32_t*)(Cp + cpoff + (long)r0 * D + col)       = l01;
                *(uint32_t*)(Cp + (long)(r0 + 8) * D + col)         = h23;
                *(uint32_t*)(Cp + cpoff + (long)(r0 + 8) * D + col) = l23;
            } else if (ATOM) {
                atomicAdd(C + (long)r0 * D + col,           v0);
                atomicAdd(C + (long)r0 * D + col + 1,       v1);
                atomicAdd(C + (long)(r0 + 8) * D + col,     v2);
                atomicAdd(C + (long)(r0 + 8) * D + col + 1, v3);
            } else {
                *(float2*)(C + (long)r0 * D + col)       = make_float2(v0, v1);
                *(float2*)(C + (long)(r0 + 8) * D + col) = make_float2(v2, v3);
            }
        }
    }
}

// ======================================================================
// Layer-0 GEMM: big n1 GEMM (y<40, BM=128) + n0 GEMM (y>=40, BM=64)
// 2-stage ring: smem 49KB (BM=128) -> 3 CTAs/SM co-reside.
// ======================================================================
__global__ void __launch_bounds__(256, 3)
layer0_gemm_kernel(const __nv_bfloat16* __restrict__ ah1,
                   const __nv_bfloat16* __restrict__ ag2,
                   const __nv_bfloat16* __restrict__ ah0,
                   const __nv_bfloat16* __restrict__ ag1,
                   const __nv_bfloat16* __restrict__ wt,
                   float* __restrict__ n1,
                   __nv_bfloat16* __restrict__ n0)
{
    extern __shared__ __align__(16) char sm[];
    const int z = blockIdx.z;
    const int bn = blockIdx.x * 64;
    const int colOff = z * HID + bn;
    const __nv_bfloat16* Bw = wt + (z ? WSZ : 0);

    if (blockIdx.y < M1 / 128) {
        const __nv_bfloat16* A = z ? ag2 : ah1;
        gemm_body<128, 1, 0, 0>(A, MOFF, Bw, blockIdx.y * 128, bn, colOff,
                                n1, nullptr, 0, sm, 0, D / 32);
    } else {
        const __nv_bfloat16* A = z ? ag1 : ah0;
        gemm_body<64, 1, 1, 0>(A, BOFF, Bw, (blockIdx.y - M1 / 128) * 64, bn, colOff,
                               nullptr, n0, BOFF, sm, 0, D / 32);
    }
}

// ---------------- layer-1 GEMM: split-K=2, fp32 atomicAdd epilogue --------
__global__ void __launch_bounds__(256, 3)
layer1_gemm_kernel(const __nv_bfloat16* __restrict__ n0,
                   const __nv_bfloat16* __restrict__ agn1,
                   const __nv_bfloat16* __restrict__ wt,
                   float* __restrict__ outb)
{
    extern __shared__ __align__(16) char sm[];
    const int z = blockIdx.z;
    const int bn = blockIdx.x * 64;
    const int ks = blockIdx.y >> 3;            // k-split half (0/1)
    const int by = blockIdx.y & 7;             // m tile
    const __nv_bfloat16* A  = z ? agn1 : n0;
    const __nv_bfloat16* Bw = wt + (z ? 3 : 2) * WSZ;
    gemm_body<64, 0, 0, 1>(A, BOFF, Bw, by * 64, bn, z * HID + bn,
                           outb, nullptr, 0, sm, ks * 8, ks * 8 + 8);
}

// ---------------- normalize rows of out[512,512], then logits ------------
__global__ void finalize_kernel(const float* __restrict__ outb,
                                const float* __restrict__ Wp,
                                const float* __restrict__ bp,
                                float* __restrict__ logits)
{
    int b = blockIdx.x;
    int t = threadIdx.x;
    __shared__ float row[D];
    __shared__ float wss[4];

    float ss = 0.f;
#pragma unroll
    for (int i = 0; i < 4; ++i) {
        int k = t + i * 128;
        float v = outb[(long)b * D + k];
        row[k] = v;
        ss += v * v;
    }
#pragma unroll
    for (int o = 16; o; o >>= 1) ss += __shfl_xor_sync(0xffffffffu, ss, o);
    if ((t & 31) == 0) wss[t >> 5] = ss;
    __syncthreads();
    float inv = 1.f / fmaxf(sqrtf(wss[0] + wss[1] + wss[2] + wss[3]), 1e-12f);

    if (t < NCLS) {
        float acc = 0.f;
#pragma unroll 8
        for (int k = 0; k < D; ++k) acc = fmaf(row[k], Wp[k * NCLS + t], acc);
        logits[(long)b * NCLS + t] = acc * inv + bp[t];
    }
}

// --------------------------------------------------------------------------
extern "C" void kernel_launch(void* const* d_in, const int* in_sizes, int n_in,
                              void* d_out, int out_size)
{
    const float* features = (const float*)d_in[0];
    const float* W_self0  = (const float*)d_in[1];
    const float* W_neigh0 = (const float*)d_in[2];
    const float* W_self1  = (const float*)d_in[3];
    const float* W_neigh1 = (const float*)d_in[4];
    const float* W_pred   = (const float*)d_in[5];
    const float* b_pred   = (const float*)d_in[6];
    const int*   samples0 = (const int*)d_in[7];
    const int*   samples1 = (const int*)d_in[8];
    const int*   samples2 = (const int*)d_in[9];
    float* logits = (float*)d_out;

    __nv_bfloat16 *ah1, *ag2, *ah0, *ag1, *n0, *agn1, *wt;
    float *n1, *outb;
    cudaGetSymbolAddress((void**)&ah1,  g_ah1);
    cudaGetSymbolAddress((void**)&ag2,  g_ag2);
    cudaGetSymbolAddress((void**)&ah0,  g_ah0);
    cudaGetSymbolAddress((void**)&ag1,  g_ag1);
    cudaGetSymbolAddress((void**)&n0,   g_n0);
    cudaGetSymbolAddress((void**)&agn1, g_agn1);
    cudaGetSymbolAddress((void**)&wt,   g_wt);
    cudaGetSymbolAddress((void**)&n1,   g_n1);
    cudaGetSymbolAddress((void**)&outb, g_out);

    constexpr int SM128 = 2 * (2 * 128 * 64 + 8192);  // 49152
    constexpr int SM64  = 2 * (2 * 64 * 64 + 8192);   // 32768
    cudaFuncSetAttribute(layer0_gemm_kernel, cudaFuncAttributeMaxDynamicSharedMemorySize, SM128);
    cudaFuncSetAttribute(layer1_gemm_kernel, cudaFuncAttributeMaxDynamicSharedMemorySize, SM64);

    // 1) all gathers / means / weight conversion in one launch
    prep_kernel<<<M1 + 2 * B + 4096, 128>>>(
        features, samples0, samples1, samples2,
        W_self0, W_neigh0, W_self1, W_neigh1,
        ah1, ag1, ah0, ag2, wt);

    // 2) layer 0: big n1 GEMM (320 CTAs) + n0 GEMM (64 CTAs) in one launch
    layer0_gemm_kernel<<<dim3(4, M1 / 128 + B / 64, 2), 256, SM128>>>(
        ah1, ag2, ah0, ag1, wt, n1, n0);

    // 3) mean of n1 groups -> planes; also zeroes outb for split-K atomics
    mean_n1_kernel<<<B, 256>>>(n1, agn1, outb);

    // 4) layer 1 GEMM, split-K=2 (128 CTAs)
    layer1_gemm_kernel<<<dim3(4, 16, 2), 256, SM64>>>(n0, agn1, wt, outb);

    // 5) row-normalize + logits
    finalize_kernel<<<B, 128>>>(outb, W_pred, b_pred, logits);
}